// round 10
// baseline (speedup 1.0000x reference)
#include <cuda_runtime.h>
#include <cuda_bf16.h>
#include <cstdint>

#define BB 128
#define TT 128
#define VV 10000
#define VP 10112
#define EE 256
#define HH 1024
#define DD 128

// ------------------- device scratch (no allocs) -------------------
__device__ __nv_bfloat16 g_ehi[(size_t)VV * EE], g_elo[(size_t)VV * EE];      // [tok][k]
__device__ __nv_bfloat16 g_gkhi[(size_t)3 * HH * EE], g_gklo[(size_t)3 * HH * EE]; // [n][k]
__device__ __nv_bfloat16 g_rkhi[(size_t)3 * HH * HH], g_rklo[(size_t)3 * HH * HH]; // [row][k]
__device__ __nv_bfloat16 g_w1hi[(size_t)DD * HH], g_w1lo[(size_t)DD * HH];    // [n][k]
__device__ __nv_bfloat16 g_w2hi[(size_t)VP * DD], g_w2lo[(size_t)VP * DD];    // [n][k]
__device__ float g_xg[(size_t)TT * BB * 3 * HH];                              // [t][b][3072]
__device__ __nv_bfloat16 g_hshi[(size_t)(TT + 1) * BB * HH];
__device__ __nv_bfloat16 g_hslo[(size_t)(TT + 1) * BB * HH];
__device__ __nv_bfloat16 g_dhi[(size_t)TT * BB * DD], g_dlo[(size_t)TT * BB * DD];
__device__ float g_logits[(size_t)TT * BB * VV];
__device__ unsigned g_bar_cnt = 0, g_bar_phase = 0;

// ------------------- helpers -------------------
__device__ __forceinline__ uint32_t smem_u32(const void* p) {
    uint32_t a;
    asm("{ .reg .u64 t; cvta.to.shared.u64 t, %1; cvt.u32.u64 %0, t; }"
        : "=r"(a) : "l"(p));
    return a;
}
__device__ __forceinline__ void ldsm4(uint32_t* r, uint32_t a) {
    asm volatile("ldmatrix.sync.aligned.m8n8.x4.shared.b16 {%0,%1,%2,%3}, [%4];"
                 : "=r"(r[0]), "=r"(r[1]), "=r"(r[2]), "=r"(r[3]) : "r"(a));
}
__device__ __forceinline__ void ldsm2(uint32_t* r, uint32_t a) {
    asm volatile("ldmatrix.sync.aligned.m8n8.x2.shared.b16 {%0,%1}, [%2];"
                 : "=r"(r[0]), "=r"(r[1]) : "r"(a));
}
__device__ __forceinline__ void mma16816(float* c, const uint32_t* a,
                                         uint32_t b0, uint32_t b1) {
    asm volatile(
        "mma.sync.aligned.m16n8k16.row.col.f32.bf16.bf16.f32 "
        "{%0,%1,%2,%3}, {%4,%5,%6,%7}, {%8,%9}, {%0,%1,%2,%3};"
        : "+f"(c[0]), "+f"(c[1]), "+f"(c[2]), "+f"(c[3])
        : "r"(a[0]), "r"(a[1]), "r"(a[2]), "r"(a[3]), "r"(b0), "r"(b1));
}
__device__ __forceinline__ void bsplit(float v, __nv_bfloat16& h, __nv_bfloat16& l) {
    h = __float2bfloat16(v);
    l = __float2bfloat16(v - __bfloat162float(h));
}
__device__ __forceinline__ float sigm(float x) { return 1.f / (1.f + __expf(-x)); }

__device__ __forceinline__ void grid_barrier(int nblk) {
    __syncthreads();
    if (threadIdx.x == 0) {
        __threadfence();
        unsigned ph = *(volatile unsigned*)&g_bar_phase;
        unsigned old = atomicAdd(&g_bar_cnt, 1);
        if (old == (unsigned)(nblk - 1)) {
            g_bar_cnt = 0;
            __threadfence();
            atomicAdd(&g_bar_phase, 1);
        } else {
            while (*(volatile unsigned*)&g_bar_phase == ph) { __nanosleep(32); }
        }
        __threadfence();
    }
    __syncthreads();
}

// =====================================================================
// k_nop: keeps the profiled launch slot on k_scan
// =====================================================================
__global__ void k_nop() {}

// =====================================================================
// k_split: pre-split weights into bf16 hi/lo, B-layouts
// =====================================================================
__global__ __launch_bounds__(256) void k_split(const float* __restrict__ emb,
                                               const float* __restrict__ gk,
                                               const float* __restrict__ rk,
                                               const float* __restrict__ w1,
                                               const float* __restrict__ w2) {
    const size_t stride = (size_t)gridDim.x * blockDim.x;
    const size_t t0 = (size_t)blockIdx.x * blockDim.x + threadIdx.x;
    for (size_t i = t0; i < (size_t)VV * EE; i += stride)
        bsplit(emb[i], g_ehi[i], g_elo[i]);
    for (size_t i = t0; i < (size_t)3 * HH * EE; i += stride) {
        int n = (int)(i % (3 * HH)), k = (int)(i / (3 * HH));
        bsplit(gk[(size_t)k * 3 * HH + n], g_gkhi[(size_t)n * EE + k],
               g_gklo[(size_t)n * EE + k]);
    }
    for (size_t i = t0; i < (size_t)3 * HH * HH; i += stride) {
        int c = (int)(i % (3 * HH)), k = (int)(i / (3 * HH));
        int row = ((c & 1023) >> 3) * 24 + (c >> 10) * 8 + (c & 7);
        bsplit(rk[(size_t)k * 3 * HH + c], g_rkhi[(size_t)row * HH + k],
               g_rklo[(size_t)row * HH + k]);
    }
    for (size_t i = t0; i < (size_t)DD * HH; i += stride) {
        int n = (int)(i % DD), k = (int)(i / DD);
        bsplit(w1[(size_t)k * DD + n], g_w1hi[(size_t)n * HH + k],
               g_w1lo[(size_t)n * HH + k]);
    }
    for (size_t i = t0; i < (size_t)VP * DD; i += stride) {
        int n = (int)(i % VP), k = (int)(i / VP);
        float v = (n < VV) ? w2[(size_t)k * VV + n] : 0.f;
        bsplit(v, g_w2hi[(size_t)n * DD + k], g_w2lo[(size_t)n * DD + k]);
    }
}

// =====================================================================
// k_xg: xg = emb[tok] @ gru_k + bi.  grid (24 n-tiles, 128 t), 256 thr
// =====================================================================
#define BP 136
#define XG_SMEM (2 * 128 * BP * 2)
__global__ void __launch_bounds__(256, 2)
k_xg(const int* __restrict__ tokens, const float* __restrict__ bi) {
    extern __shared__ __nv_bfloat16 xsm[];
    __nv_bfloat16* Bhi = xsm;
    __nv_bfloat16* Blo = Bhi + 128 * BP;
    __shared__ float sb[128];
    __shared__ int toks[128];
    const int tid = threadIdx.x, wid = tid >> 5, lane = tid & 31;
    const int t = blockIdx.y, n0 = blockIdx.x * 128;
    if (tid < 128) {
        sb[tid] = bi[n0 + tid];
        toks[tid] = tokens[tid * TT + t];
    }
    __syncthreads();
    const int r0 = wid * 16 + (lane >> 2);
    const int kq = (lane & 3) * 2;
    const __nv_bfloat16* eh0 = g_ehi + (size_t)toks[r0] * EE;
    const __nv_bfloat16* eh1 = g_ehi + (size_t)toks[r0 + 8] * EE;
    const __nv_bfloat16* el0 = g_elo + (size_t)toks[r0] * EE;
    const __nv_bfloat16* el1 = g_elo + (size_t)toks[r0 + 8] * EE;

    float acc[16][4];
#pragma unroll
    for (int i = 0; i < 16; i++)
#pragma unroll
        for (int j = 0; j < 4; j++) acc[i][j] = 0.f;
    const int br15 = lane & 15, bh8 = lane >> 4;
    const int lr = tid >> 1, lp = tid & 1;

    for (int kc = 0; kc < 2; kc++) {
        if (kc) __syncthreads();
        {
            const __nv_bfloat16* sh = g_gkhi + (size_t)(n0 + lr) * EE + kc * 128 + lp * 64;
            const __nv_bfloat16* sl = g_gklo + (size_t)(n0 + lr) * EE + kc * 128 + lp * 64;
#pragma unroll
            for (int j = 0; j < 64; j += 8) {
                *(uint4*)(Bhi + lr * BP + lp * 64 + j) = *(const uint4*)(sh + j);
                *(uint4*)(Blo + lr * BP + lp * 64 + j) = *(const uint4*)(sl + j);
            }
        }
        __syncthreads();
#pragma unroll
        for (int kt = 0; kt < 8; kt++) {
            const int k0 = kc * 128 + kt * 16 + kq;
            uint32_t ah[4], al[4];
            ah[0] = *(const uint32_t*)(eh0 + k0);
            ah[1] = *(const uint32_t*)(eh1 + k0);
            ah[2] = *(const uint32_t*)(eh0 + k0 + 8);
            ah[3] = *(const uint32_t*)(eh1 + k0 + 8);
            al[0] = *(const uint32_t*)(el0 + k0);
            al[1] = *(const uint32_t*)(el1 + k0);
            al[2] = *(const uint32_t*)(el0 + k0 + 8);
            al[3] = *(const uint32_t*)(el1 + k0 + 8);
#pragma unroll
            for (int p = 0; p < 8; p++) {
                uint32_t bh[4], bl[4];
                ldsm4(bh, smem_u32(Bhi + (p * 16 + br15) * BP + kt * 16 + bh8 * 8));
                ldsm4(bl, smem_u32(Blo + (p * 16 + br15) * BP + kt * 16 + bh8 * 8));
                mma16816(acc[2 * p], ah, bh[0], bh[2]);
                mma16816(acc[2 * p], ah, bl[0], bl[2]);
                mma16816(acc[2 * p], al, bh[0], bh[2]);
                mma16816(acc[2 * p + 1], ah, bh[1], bh[3]);
                mma16816(acc[2 * p + 1], ah, bl[1], bl[3]);
                mma16816(acc[2 * p + 1], al, bh[1], bh[3]);
            }
        }
    }
    const int rr = wid * 16 + (lane >> 2), cc = 2 * (lane & 3);
    float* outb = g_xg + (size_t)t * BB * 3072 + n0;
#pragma unroll
    for (int p = 0; p < 16; p++) {
        int col = p * 8 + cc;
        float2 v0 = {acc[p][0] + sb[col], acc[p][1] + sb[col + 1]};
        float2 v1 = {acc[p][2] + sb[col], acc[p][3] + sb[col + 1]};
        *(float2*)(outb + (size_t)rr * 3072 + col) = v0;
        *(float2*)(outb + (size_t)(rr + 8) * 3072 + col) = v1;
    }
}

// =====================================================================
// k_scan: persistent GRU scan, warp-private A staging with COALESCED
// h loads (8 lanes/row = 1 full line per 8 lanes; 4 lines/LDG vs 16).
// No per-thread threadfence (barrier's leader fence is the release).
// =====================================================================
#define SC_NB 128
#define SC_WP 1032
#define AW_P 72
#define SCAN_SMEM ((2 * 24 * SC_WP + 8 * 4608) * 2)
__global__ void __launch_bounds__(256, 1) k_scan(const float* __restrict__ br) {
    extern __shared__ __nv_bfloat16 ssm[];
    __nv_bfloat16* Whi = ssm;
    __nv_bfloat16* Wlo = Whi + 24 * SC_WP;
    __nv_bfloat16* AB = Wlo + 24 * SC_WP;
    const int tid = threadIdx.x, wid = tid >> 5, lane = tid & 31;
    const int bid = blockIdx.x, u0 = bid * 8;

    for (int i = tid; i < 24 * 128; i += 256) {
        int n = i >> 7, j = (i & 127) * 8;
        *(uint4*)(Whi + n * SC_WP + j) = *(const uint4*)(g_rkhi + ((size_t)(bid * 24 + n)) * HH + j);
        *(uint4*)(Wlo + n * SC_WP + j) = *(const uint4*)(g_rklo + ((size_t)(bid * 24 + n)) * HH + j);
    }
    for (int i = tid; i < 128; i += 256) {
        uint4 z = {0, 0, 0, 0};
        *(uint4*)(g_hshi + (size_t)bid * HH + i * 8) = z;
        *(uint4*)(g_hslo + (size_t)bid * HH + i * 8) = z;
    }
    const int cc = 2 * (lane & 3);
    const float bz0 = br[u0 + cc], bz1 = br[u0 + cc + 1];
    const float brr0 = br[HH + u0 + cc], brr1 = br[HH + u0 + cc + 1];
    const float bh0 = br[2 * HH + u0 + cc], bh1 = br[2 * HH + u0 + cc + 1];
    float hp[4] = {0.f, 0.f, 0.f, 0.f};
    const int r1 = wid * 16 + (lane >> 2);
    const int b15 = lane & 15, bh8 = lane >> 4;
    const int b7 = lane & 7, bq = (lane >> 3) & 1;
    // coalesced staging map: 8 lanes per row, 4 row-groups of 4 rows
    const int lrow = lane >> 3;          // 0..3
    const int lcol = (lane & 7) * 8;     // bf16 units, 16B per lane
    __nv_bfloat16* AW = AB + wid * 4608;
    const uint32_t aAddrBase = smem_u32(AW + (lane & 15) * AW_P + (lane >> 4) * 8);
    __nv_bfloat16* dstBase = AW + lrow * AW_P + lcol;
    const size_t hOff = (size_t)(wid * 16 + lrow) * HH + lcol;
    grid_barrier(SC_NB);

    for (int t = 0; t < TT; t++) {
        const float* xb = g_xg + (size_t)t * BB * 3072;
        float2 xz1 = *(const float2*)(xb + (size_t)r1 * 3072 + u0 + cc);
        float2 xr1 = *(const float2*)(xb + (size_t)r1 * 3072 + HH + u0 + cc);
        float2 xh1 = *(const float2*)(xb + (size_t)r1 * 3072 + 2 * HH + u0 + cc);
        float2 xz2 = *(const float2*)(xb + (size_t)(r1 + 8) * 3072 + u0 + cc);
        float2 xr2 = *(const float2*)(xb + (size_t)(r1 + 8) * 3072 + HH + u0 + cc);
        float2 xh2 = *(const float2*)(xb + (size_t)(r1 + 8) * 3072 + 2 * HH + u0 + cc);

        const __nv_bfloat16* Hhi = g_hshi + (size_t)t * BB * HH + hOff;
        const __nv_bfloat16* Hlo = g_hslo + (size_t)t * BB * HH + hOff;
        float acc[3][4];
#pragma unroll
        for (int i = 0; i < 3; i++)
#pragma unroll
            for (int j = 0; j < 4; j++) acc[i][j] = 0.f;

        uint4 ph[4], pl[4];
#pragma unroll
        for (int rg = 0; rg < 4; rg++) {
            ph[rg] = *(const uint4*)(Hhi + (size_t)rg * 4 * HH);
            pl[rg] = *(const uint4*)(Hlo + (size_t)rg * 4 * HH);
        }
#pragma unroll
        for (int rg = 0; rg < 4; rg++) {
            *(uint4*)(dstBase + rg * 4 * AW_P) = ph[rg];
            *(uint4*)(dstBase + 1152 + rg * 4 * AW_P) = pl[rg];
        }
        __syncwarp();

        for (int c = 0; c < 16; c++) {
            if (c < 15) {
#pragma unroll
                for (int rg = 0; rg < 4; rg++) {
                    ph[rg] = *(const uint4*)(Hhi + (size_t)rg * 4 * HH + (c + 1) * 64);
                    pl[rg] = *(const uint4*)(Hlo + (size_t)rg * 4 * HH + (c + 1) * 64);
                }
            }
            const uint32_t aHi = aAddrBase + (uint32_t)((c & 1) * 2304 * 2);
            const uint32_t aLo = aHi + 1152 * 2;
#pragma unroll
            for (int kk = 0; kk < 4; kk++) {
                uint32_t ah[4], al[4];
                ldsm4(ah, aHi + kk * 32);
                ldsm4(al, aLo + kk * 32);
                const int kcol = c * 64 + kk * 16;
                uint32_t wh[4], wl[4], w2h[2], w2l[2];
                ldsm4(wh, smem_u32(Whi + b15 * SC_WP + kcol + bh8 * 8));
                ldsm4(wl, smem_u32(Wlo + b15 * SC_WP + kcol + bh8 * 8));
                ldsm2(w2h, smem_u32(Whi + (16 + b7) * SC_WP + kcol + bq * 8));
                ldsm2(w2l, smem_u32(Wlo + (16 + b7) * SC_WP + kcol + bq * 8));
                mma16816(acc[0], ah, wh[0], wh[2]);
                mma16816(acc[0], ah, wl[0], wl[2]);
                mma16816(acc[0], al, wh[0], wh[2]);
                mma16816(acc[1], ah, wh[1], wh[3]);
                mma16816(acc[1], ah, wl[1], wl[3]);
                mma16816(acc[1], al, wh[1], wh[3]);
                mma16816(acc[2], ah, w2h[0], w2h[1]);
                mma16816(acc[2], ah, w2l[0], w2l[1]);
                mma16816(acc[2], al, w2h[0], w2h[1]);
            }
            if (c < 15) {
                __nv_bfloat16* d = AW + ((c + 1) & 1) * 2304 + lrow * AW_P + lcol;
#pragma unroll
                for (int rg = 0; rg < 4; rg++) {
                    *(uint4*)(d + rg * 4 * AW_P) = ph[rg];
                    *(uint4*)(d + 1152 + rg * 4 * AW_P) = pl[rg];
                }
            }
            __syncwarp();
        }
        {
            float z, r, hh;
            z = sigm(xz1.x + acc[0][0] + bz0);
            r = sigm(xr1.x + acc[1][0] + brr0);
            hh = tanhf(xh1.x + r * (acc[2][0] + bh0));
            hp[0] = z * hp[0] + (1.f - z) * hh;
            z = sigm(xz1.y + acc[0][1] + bz1);
            r = sigm(xr1.y + acc[1][1] + brr1);
            hh = tanhf(xh1.y + r * (acc[2][1] + bh1));
            hp[1] = z * hp[1] + (1.f - z) * hh;
            z = sigm(xz2.x + acc[0][2] + bz0);
            r = sigm(xr2.x + acc[1][2] + brr0);
            hh = tanhf(xh2.x + r * (acc[2][2] + bh0));
            hp[2] = z * hp[2] + (1.f - z) * hh;
            z = sigm(xz2.y + acc[0][3] + bz1);
            r = sigm(xr2.y + acc[1][3] + brr1);
            hh = tanhf(xh2.y + r * (acc[2][3] + bh1));
            hp[3] = z * hp[3] + (1.f - z) * hh;

            __nv_bfloat16 h0, l0, h1, l1;
            bsplit(hp[0], h0, l0); bsplit(hp[1], h1, l1);
            size_t o1 = ((size_t)(t + 1) * BB + r1) * HH + u0 + cc;
            *(__nv_bfloat162*)(g_hshi + o1) = __nv_bfloat162(h0, h1);
            *(__nv_bfloat162*)(g_hslo + o1) = __nv_bfloat162(l0, l1);
            bsplit(hp[2], h0, l0); bsplit(hp[3], h1, l1);
            size_t o2 = ((size_t)(t + 1) * BB + r1 + 8) * HH + u0 + cc;
            *(__nv_bfloat162*)(g_hshi + o2) = __nv_bfloat162(h0, h1);
            *(__nv_bfloat162*)(g_hslo + o2) = __nv_bfloat162(l0, l1);
        }
        grid_barrier(SC_NB);
    }
}

// =====================================================================
// k_mlp: d = relu(hs @ w1 + b1). grid (2 n-halves, 128 t), 256 thr, occ 2
// =====================================================================
#define MP 72
#define MLP_SMEM ((128 * MP + 64 * MP) * 2 * 2)
__global__ void __launch_bounds__(256, 2) k_mlp(const float* __restrict__ b1) {
    extern __shared__ __nv_bfloat16 msm[];
    __nv_bfloat16* Ahi = msm;
    __nv_bfloat16* Alo = Ahi + 128 * MP;
    __nv_bfloat16* Bhi = Alo + 128 * MP;
    __nv_bfloat16* Blo = Bhi + 64 * MP;
    __shared__ float sb[64];
    const int tid = threadIdx.x, wid = tid >> 5, lane = tid & 31;
    const int t = blockIdx.y, n0 = blockIdx.x * 64;
    if (tid < 64) sb[tid] = b1[n0 + tid];
    float acc[8][4];
#pragma unroll
    for (int i = 0; i < 8; i++)
#pragma unroll
        for (int j = 0; j < 4; j++) acc[i][j] = 0.f;
    const int arow = wid * 16 + (lane & 15), ahalf = lane >> 4;
    const int br15 = lane & 15, bh8 = lane >> 4;
    const int ar = tid >> 1, ap = (tid & 1) * 32;
    const int brr = tid >> 2, bp = (tid & 3) * 16;

    for (int kc = 0; kc < 16; kc++) {
        if (kc) __syncthreads();
        {
            const __nv_bfloat16* sh = g_hshi + ((size_t)(t + 1) * BB + ar) * HH + kc * 64 + ap;
            const __nv_bfloat16* sl = g_hslo + ((size_t)(t + 1) * BB + ar) * HH + kc * 64 + ap;
            *(uint4*)(Ahi + ar * MP + ap) = *(const uint4*)(sh);
            *(uint4*)(Ahi + ar * MP + ap + 8) = *(const uint4*)(sh + 8);
            *(uint4*)(Ahi + ar * MP + ap + 16) = *(const uint4*)(sh + 16);
            *(uint4*)(Ahi + ar * MP + ap + 24) = *(const uint4*)(sh + 24);
            *(uint4*)(Alo + ar * MP + ap) = *(const uint4*)(sl);
            *(uint4*)(Alo + ar * MP + ap + 8) = *(const uint4*)(sl + 8);
            *(uint4*)(Alo + ar * MP + ap + 16) = *(const uint4*)(sl + 16);
            *(uint4*)(Alo + ar * MP + ap + 24) = *(const uint4*)(sl + 24);
            const __nv_bfloat16* wh = g_w1hi + (size_t)(n0 + brr) * HH + kc * 64 + bp;
            const __nv_bfloat16* wl = g_w1lo + (size_t)(n0 + brr) * HH + kc * 64 + bp;
            *(uint4*)(Bhi + brr * MP + bp) = *(const uint4*)(wh);
            *(uint4*)(Bhi + brr * MP + bp + 8) = *(const uint4*)(wh + 8);
            *(uint4*)(Blo + brr * MP + bp) = *(const uint4*)(wl);
            *(uint4*)(Blo + brr * MP + bp + 8) = *(const uint4*)(wl + 8);
        }
        __syncthreads();
#pragma unroll
        for (int kk = 0; kk < 4; kk++) {
            uint32_t ah[4], al[4];
            ldsm4(ah, smem_u32(Ahi + arow * MP + ahalf * 8 + kk * 16));
            ldsm4(al, smem_u32(Alo + arow * MP + ahalf * 8 + kk * 16));
#pragma unroll
            for (int p = 0; p < 4; p++) {
                uint32_t bh[4], bl[4];
                ldsm4(bh, smem_u32(Bhi + (p * 16 + br15) * MP + kk * 16 + bh8 * 8));
                ldsm4(bl, smem_u32(Blo + (p * 16 + br15) * MP + kk * 16 + bh8 * 8));
                mma16816(acc[2 * p], ah, bh[0], bh[2]);
                mma16816(acc[2 * p], ah, bl[0], bl[2]);
                mma16816(acc[2 * p], al, bh[0], bh[2]);
                mma16816(acc[2 * p + 1], ah, bh[1], bh[3]);
                mma16816(acc[2 * p + 1], ah, bl[1], bl[3]);
                mma16816(acc[2 * p + 1], al, bh[1], bh[3]);
            }
        }
    }
    const int rr = wid * 16 + (lane >> 2), cc = 2 * (lane & 3);
    const int m1 = t * BB + rr, m2 = m1 + 8;
#pragma unroll
    for (int p = 0; p < 8; p++) {
        int col = p * 8 + cc;
        float d0 = fmaxf(acc[p][0] + sb[col], 0.f);
        float d1 = fmaxf(acc[p][1] + sb[col + 1], 0.f);
        float d2 = fmaxf(acc[p][2] + sb[col], 0.f);
        float d3 = fmaxf(acc[p][3] + sb[col + 1], 0.f);
        __nv_bfloat16 h0, l0, h1, l1;
        bsplit(d0, h0, l0); bsplit(d1, h1, l1);
        *(__nv_bfloat162*)(g_dhi + (size_t)m1 * DD + n0 + col) = __nv_bfloat162(h0, h1);
        *(__nv_bfloat162*)(g_dlo + (size_t)m1 * DD + n0 + col) = __nv_bfloat162(l0, l1);
        bsplit(d2, h0, l0); bsplit(d3, h1, l1);
        *(__nv_bfloat162*)(g_dhi + (size_t)m2 * DD + n0 + col) = __nv_bfloat162(h0, h1);
        *(__nv_bfloat162*)(g_dlo + (size_t)m2 * DD + n0 + col) = __nv_bfloat162(l0, l1);
    }
}

// =====================================================================
// k_logits v2: logits = d @ w2 + b2. grid (158 n-tiles of 64, 128 m).
// A fragments preloaded into registers (no loads in MMA loop), occ 2.
// =====================================================================
#define LBP 136
#define LG_SMEM (2 * 64 * LBP * 2)
__global__ void __launch_bounds__(256, 2) k_logits(const float* __restrict__ b2) {
    extern __shared__ __nv_bfloat16 lsm[];
    __nv_bfloat16* Bhi = lsm;
    __nv_bfloat16* Blo = Bhi + 64 * LBP;
    __shared__ float sb[64];
    const int tid = threadIdx.x, wid = tid >> 5, lane = tid & 31;
    const int m0 = blockIdx.y * 128, n0 = blockIdx.x * 64;
    if (tid < 64) sb[tid] = (n0 + tid < VV) ? b2[n0 + tid] : 0.f;
    {   // B: 64 rows x 128 k, each thread one quarter-row
        const int row = tid >> 2, part = (tid & 3) * 32;
        const __nv_bfloat16* wh = g_w2hi + (size_t)(n0 + row) * DD + part;
        const __nv_bfloat16* wl = g_w2lo + (size_t)(n0 + row) * DD + part;
#pragma unroll
        for (int j = 0; j < 32; j += 8) {
            *(uint4*)(Bhi + row * LBP + part + j) = *(const uint4*)(wh + j);
            *(uint4*)(Blo + row * LBP + part + j) = *(const uint4*)(wl + j);
        }
    }
    // A fragments preloaded to registers (K=128 -> 8 kt)
    const int r0 = wid * 16 + (lane >> 2);
    const int kq = (lane & 3) * 2;
    const __nv_bfloat16* dh0 = g_dhi + (size_t)(m0 + r0) * DD;
    const __nv_bfloat16* dh1 = g_dhi + (size_t)(m0 + r0 + 8) * DD;
    const __nv_bfloat16* dl0 = g_dlo + (size_t)(m0 + r0) * DD;
    const __nv_bfloat16* dl1 = g_dlo + (size_t)(m0 + r0 + 8) * DD;
    uint32_t Ah[8][4], Al[8][4];
#pragma unroll
    for (int kt = 0; kt < 8; kt++) {
        const int k0 = kt * 16 + kq;
        Ah[kt][0] = *(const uint32_t*)(dh0 + k0);
        Ah[kt][1] = *(const uint32_t*)(dh1 + k0);
        Ah[kt][2] = *(const uint32_t*)(dh0 + k0 + 8);
        Ah[kt][3] = *(const uint32_t*)(dh1 + k0 + 8);
        Al[kt][0] = *(const uint32_t*)(dl0 + k0);
        Al[kt][1] = *(const uint32_t*)(dl1 + k0);
        Al[kt][2] = *(const uint32_t*)(dl0 + k0 + 8);
        Al[kt][3] = *(const uint32_t*)(dl1 + k0 + 8);
    }
    __syncthreads();
    float acc[8][4];
#pragma unroll
    for (int i = 0; i < 8; i++)
#pragma unroll
        for (int j = 0; j < 4; j++) acc[i][j] = 0.f;
    const int br15 = lane & 15, bh8 = lane >> 4;
#pragma unroll
    for (int kt = 0; kt < 8; kt++) {
#pragma unroll
        for (int p = 0; p < 4; p++) {
            uint32_t bh[4], bl[4];
            ldsm4(bh, smem_u32(Bhi + (p * 16 + br15) * LBP + kt * 16 + bh8 * 8));
            ldsm4(bl, smem_u32(Blo + (p * 16 + br15) * LBP + kt * 16 + bh8 * 8));
            mma16816(acc[2 * p], Ah[kt], bh[0], bh[2]);
            mma16816(acc[2 * p], Ah[kt], bl[0], bl[2]);
            mma16816(acc[2 * p], Al[kt], bh[0], bh[2]);
            mma16816(acc[2 * p + 1], Ah[kt], bh[1], bh[3]);
            mma16816(acc[2 * p + 1], Ah[kt], bl[1], bl[3]);
            mma16816(acc[2 * p + 1], Al[kt], bh[1], bh[3]);
        }
    }
    const int rr = wid * 16 + (lane >> 2), cc = 2 * (lane & 3);
    float* o1 = g_logits + (size_t)(m0 + rr) * VV;
    float* o2 = g_logits + (size_t)(m0 + rr + 8) * VV;
#pragma unroll
    for (int p = 0; p < 8; p++) {
        int col = n0 + p * 8 + cc;
        if (col < VV) {
            float2 v0 = {acc[p][0] + sb[p * 8 + cc], acc[p][1] + sb[p * 8 + cc + 1]};
            float2 v1 = {acc[p][2] + sb[p * 8 + cc], acc[p][3] + sb[p * 8 + cc + 1]};
            *(float2*)(o1 + col) = v0;
            *(float2*)(o2 + col) = v1;
        }
    }
}

// =====================================================================
// k_softmax: online max+sum pass, then normalize-write. TEMP=0.02
// =====================================================================
__global__ __launch_bounds__(256) void k_softmax(float* __restrict__ out) {
    const int m = blockIdx.x;
    const int b = m & 127, t = m >> 7;
    const float* lr = g_logits + (size_t)m * VV;
    float* orow = out + ((size_t)b * TT + t) * VV;
    __shared__ float rm[8], rs[8];
    const int tid = threadIdx.x, lane = tid & 31, wid = tid >> 5;
    float mx = -1e30f, s = 0.f;
    for (int v = tid; v < VV; v += 256) {
        float x = lr[v] * 50.f;
        float nm = fmaxf(mx, x);
        s = s * __expf(mx - nm) + __expf(x - nm);
        mx = nm;
    }
#pragma unroll
    for (int o = 16; o; o >>= 1) {
        float om = __shfl_xor_sync(~0u, mx, o);
        float os = __shfl_xor_sync(~0u, s, o);
        float nm = fmaxf(mx, om);
        s = s * __expf(mx - nm) + os * __expf(om - nm);
        mx = nm;
    }
    if (lane == 0) { rm[wid] = mx; rs[wid] = s; }
    __syncthreads();
    if (tid == 0) {
        float M = rm[0], S = rs[0];
#pragma unroll
        for (int i = 1; i < 8; i++) {
            float nm = fmaxf(M, rm[i]);
            S = S * __expf(M - nm) + rs[i] * __expf(rm[i] - nm);
            M = nm;
        }
        rm[0] = M; rs[0] = 1.f / S;
    }
    __syncthreads();
    mx = rm[0];
    float inv = rs[0];
    for (int v = tid; v < VV; v += 256)
        orow[v] = __expf(lr[v] * 50.f - mx) * inv;
}

// =====================================================================
extern "C" void kernel_launch(void* const* d_in, const int* in_sizes, int n_in,
                              void* d_out, int out_size) {
    const int* tokens   = (const int*)d_in[0];
    const float* emb    = (const float*)d_in[1];
    const float* gru_k  = (const float*)d_in[2];
    const float* gru_rk = (const float*)d_in[3];
    const float* gru_bi = (const float*)d_in[4];
    const float* gru_br = (const float*)d_in[5];
    const float* w1     = (const float*)d_in[6];
    const float* b1     = (const float*)d_in[7];
    const float* w2     = (const float*)d_in[8];
    const float* b2     = (const float*)d_in[9];
    float* out = (float*)d_out;

    cudaFuncSetAttribute(k_xg, cudaFuncAttributeMaxDynamicSharedMemorySize, XG_SMEM);
    cudaFuncSetAttribute(k_scan, cudaFuncAttributeMaxDynamicSharedMemorySize, SCAN_SMEM);
    cudaFuncSetAttribute(k_mlp, cudaFuncAttributeMaxDynamicSharedMemorySize, MLP_SMEM);
    cudaFuncSetAttribute(k_logits, cudaFuncAttributeMaxDynamicSharedMemorySize, LG_SMEM);

    k_split<<<2048, 256>>>(emb, gru_k, gru_rk, w1, w2);
    k_xg<<<dim3(24, 128), 256, XG_SMEM>>>(tokens, gru_bi);
    k_nop<<<1, 1>>>();
    k_scan<<<SC_NB, 256, SCAN_SMEM>>>(gru_br);
    k_mlp<<<dim3(2, 128), 256, MLP_SMEM>>>(b1);
    k_logits<<<dim3(158, 128), 256, LG_SMEM>>>(b2);
    k_softmax<<<TT * BB, 256>>>(out);
}

// round 11
// speedup vs baseline: 1.1573x; 1.1573x over previous
#include <cuda_runtime.h>
#include <cuda_bf16.h>
#include <cstdint>

#define BB 128
#define TT 128
#define VV 10000
#define VP 10112
#define EE 256
#define HH 1024
#define DD 128

// ------------------- device scratch (no allocs) -------------------
__device__ __nv_bfloat16 g_ehi[(size_t)VV * EE], g_elo[(size_t)VV * EE];      // [tok][k]
__device__ __nv_bfloat16 g_gkhi[(size_t)3 * HH * EE], g_gklo[(size_t)3 * HH * EE]; // [n][k]
__device__ __nv_bfloat16 g_rkhi[(size_t)3 * HH * HH], g_rklo[(size_t)3 * HH * HH]; // [row][k]
__device__ __nv_bfloat16 g_w1hi[(size_t)DD * HH], g_w1lo[(size_t)DD * HH];    // [n][k]
__device__ __nv_bfloat16 g_w2hi[(size_t)VP * DD], g_w2lo[(size_t)VP * DD];    // [n][k]
__device__ float g_xg[(size_t)TT * BB * 3 * HH];                              // [t][b][3072]
__device__ __nv_bfloat16 g_hshi[(size_t)(TT + 1) * BB * HH];
__device__ __nv_bfloat16 g_hslo[(size_t)(TT + 1) * BB * HH];
__device__ __nv_bfloat16 g_dhi[(size_t)TT * BB * DD], g_dlo[(size_t)TT * BB * DD];
__device__ float g_logits[(size_t)TT * BB * VV];
__device__ unsigned g_bar_cnt = 0, g_bar_phase = 0;

// ------------------- helpers -------------------
__device__ __forceinline__ uint32_t smem_u32(const void* p) {
    uint32_t a;
    asm("{ .reg .u64 t; cvta.to.shared.u64 t, %1; cvt.u32.u64 %0, t; }"
        : "=r"(a) : "l"(p));
    return a;
}
__device__ __forceinline__ void ldsm4(uint32_t* r, uint32_t a) {
    asm volatile("ldmatrix.sync.aligned.m8n8.x4.shared.b16 {%0,%1,%2,%3}, [%4];"
                 : "=r"(r[0]), "=r"(r[1]), "=r"(r[2]), "=r"(r[3]) : "r"(a));
}
__device__ __forceinline__ void ldsm2(uint32_t* r, uint32_t a) {
    asm volatile("ldmatrix.sync.aligned.m8n8.x2.shared.b16 {%0,%1}, [%2];"
                 : "=r"(r[0]), "=r"(r[1]) : "r"(a));
}
__device__ __forceinline__ void mma16816(float* c, const uint32_t* a,
                                         uint32_t b0, uint32_t b1) {
    asm volatile(
        "mma.sync.aligned.m16n8k16.row.col.f32.bf16.bf16.f32 "
        "{%0,%1,%2,%3}, {%4,%5,%6,%7}, {%8,%9}, {%0,%1,%2,%3};"
        : "+f"(c[0]), "+f"(c[1]), "+f"(c[2]), "+f"(c[3])
        : "r"(a[0]), "r"(a[1]), "r"(a[2]), "r"(a[3]), "r"(b0), "r"(b1));
}
__device__ __forceinline__ void bsplit(float v, __nv_bfloat16& h, __nv_bfloat16& l) {
    h = __float2bfloat16(v);
    l = __float2bfloat16(v - __bfloat162float(h));
}
__device__ __forceinline__ float sigm(float x) { return 1.f / (1.f + __expf(-x)); }

__device__ __forceinline__ void grid_barrier(int nblk) {
    __syncthreads();
    if (threadIdx.x == 0) {
        __threadfence();
        unsigned ph = *(volatile unsigned*)&g_bar_phase;
        unsigned old = atomicAdd(&g_bar_cnt, 1);
        if (old == (unsigned)(nblk - 1)) {
            g_bar_cnt = 0;
            __threadfence();
            atomicAdd(&g_bar_phase, 1);
        } else {
            while (*(volatile unsigned*)&g_bar_phase == ph) { __nanosleep(32); }
        }
        __threadfence();
    }
    __syncthreads();
}

// =====================================================================
// k_split: pre-split weights into bf16 hi/lo, B-layouts
// =====================================================================
__global__ __launch_bounds__(256) void k_split(const float* __restrict__ emb,
                                               const float* __restrict__ gk,
                                               const float* __restrict__ rk,
                                               const float* __restrict__ w1,
                                               const float* __restrict__ w2) {
    const size_t stride = (size_t)gridDim.x * blockDim.x;
    const size_t t0 = (size_t)blockIdx.x * blockDim.x + threadIdx.x;
    for (size_t i = t0; i < (size_t)VV * EE; i += stride)
        bsplit(emb[i], g_ehi[i], g_elo[i]);
    for (size_t i = t0; i < (size_t)3 * HH * EE; i += stride) {
        int n = (int)(i % (3 * HH)), k = (int)(i / (3 * HH));
        bsplit(gk[(size_t)k * 3 * HH + n], g_gkhi[(size_t)n * EE + k],
               g_gklo[(size_t)n * EE + k]);
    }
    for (size_t i = t0; i < (size_t)3 * HH * HH; i += stride) {
        int c = (int)(i % (3 * HH)), k = (int)(i / (3 * HH));
        int row = ((c & 1023) >> 3) * 24 + (c >> 10) * 8 + (c & 7);
        bsplit(rk[(size_t)k * 3 * HH + c], g_rkhi[(size_t)row * HH + k],
               g_rklo[(size_t)row * HH + k]);
    }
    for (size_t i = t0; i < (size_t)DD * HH; i += stride) {
        int n = (int)(i % DD), k = (int)(i / DD);
        bsplit(w1[(size_t)k * DD + n], g_w1hi[(size_t)n * HH + k],
               g_w1lo[(size_t)n * HH + k]);
    }
    for (size_t i = t0; i < (size_t)VP * DD; i += stride) {
        int n = (int)(i % VP), k = (int)(i / VP);
        float v = (n < VV) ? w2[(size_t)k * VV + n] : 0.f;
        bsplit(v, g_w2hi[(size_t)n * DD + k], g_w2lo[(size_t)n * DD + k]);
    }
}

// =====================================================================
// k_xg: xg = emb[tok] @ gru_k + bi.  grid (24 n-tiles, 128 t), 256 thr
// =====================================================================
#define BP 136
#define XG_SMEM (2 * 128 * BP * 2)
__global__ void __launch_bounds__(256, 2)
k_xg(const int* __restrict__ tokens, const float* __restrict__ bi) {
    extern __shared__ __nv_bfloat16 xsm[];
    __nv_bfloat16* Bhi = xsm;
    __nv_bfloat16* Blo = Bhi + 128 * BP;
    __shared__ float sb[128];
    __shared__ int toks[128];
    const int tid = threadIdx.x, wid = tid >> 5, lane = tid & 31;
    const int t = blockIdx.y, n0 = blockIdx.x * 128;
    if (tid < 128) {
        sb[tid] = bi[n0 + tid];
        toks[tid] = tokens[tid * TT + t];
    }
    __syncthreads();
    const int r0 = wid * 16 + (lane >> 2);
    const int kq = (lane & 3) * 2;
    const __nv_bfloat16* eh0 = g_ehi + (size_t)toks[r0] * EE;
    const __nv_bfloat16* eh1 = g_ehi + (size_t)toks[r0 + 8] * EE;
    const __nv_bfloat16* el0 = g_elo + (size_t)toks[r0] * EE;
    const __nv_bfloat16* el1 = g_elo + (size_t)toks[r0 + 8] * EE;

    float acc[16][4];
#pragma unroll
    for (int i = 0; i < 16; i++)
#pragma unroll
        for (int j = 0; j < 4; j++) acc[i][j] = 0.f;
    const int br15 = lane & 15, bh8 = lane >> 4;
    const int lr = tid >> 1, lp = tid & 1;

    for (int kc = 0; kc < 2; kc++) {
        if (kc) __syncthreads();
        {
            const __nv_bfloat16* sh = g_gkhi + (size_t)(n0 + lr) * EE + kc * 128 + lp * 64;
            const __nv_bfloat16* sl = g_gklo + (size_t)(n0 + lr) * EE + kc * 128 + lp * 64;
#pragma unroll
            for (int j = 0; j < 64; j += 8) {
                *(uint4*)(Bhi + lr * BP + lp * 64 + j) = *(const uint4*)(sh + j);
                *(uint4*)(Blo + lr * BP + lp * 64 + j) = *(const uint4*)(sl + j);
            }
        }
        __syncthreads();
#pragma unroll
        for (int kt = 0; kt < 8; kt++) {
            const int k0 = kc * 128 + kt * 16 + kq;
            uint32_t ah[4], al[4];
            ah[0] = *(const uint32_t*)(eh0 + k0);
            ah[1] = *(const uint32_t*)(eh1 + k0);
            ah[2] = *(const uint32_t*)(eh0 + k0 + 8);
            ah[3] = *(const uint32_t*)(eh1 + k0 + 8);
            al[0] = *(const uint32_t*)(el0 + k0);
            al[1] = *(const uint32_t*)(el1 + k0);
            al[2] = *(const uint32_t*)(el0 + k0 + 8);
            al[3] = *(const uint32_t*)(el1 + k0 + 8);
#pragma unroll
            for (int p = 0; p < 8; p++) {
                uint32_t bh[4], bl[4];
                ldsm4(bh, smem_u32(Bhi + (p * 16 + br15) * BP + kt * 16 + bh8 * 8));
                ldsm4(bl, smem_u32(Blo + (p * 16 + br15) * BP + kt * 16 + bh8 * 8));
                mma16816(acc[2 * p], ah, bh[0], bh[2]);
                mma16816(acc[2 * p], ah, bl[0], bl[2]);
                mma16816(acc[2 * p], al, bh[0], bh[2]);
                mma16816(acc[2 * p + 1], ah, bh[1], bh[3]);
                mma16816(acc[2 * p + 1], ah, bl[1], bl[3]);
                mma16816(acc[2 * p + 1], al, bh[1], bh[3]);
            }
        }
    }
    const int rr = wid * 16 + (lane >> 2), cc = 2 * (lane & 3);
    float* outb = g_xg + (size_t)t * BB * 3072 + n0;
#pragma unroll
    for (int p = 0; p < 16; p++) {
        int col = p * 8 + cc;
        float2 v0 = {acc[p][0] + sb[col], acc[p][1] + sb[col + 1]};
        float2 v1 = {acc[p][2] + sb[col], acc[p][3] + sb[col + 1]};
        *(float2*)(outb + (size_t)rr * 3072 + col) = v0;
        *(float2*)(outb + (size_t)(rr + 8) * 3072 + col) = v1;
    }
}

// =====================================================================
// k_scan: R5 version — persistent GRU scan, warp-private A staging
// (LDG->STS double buffer), no block syncs inside k-loop.
// =====================================================================
#define SC_NB 128
#define SC_WP 1032
#define AW_P 72
#define SCAN_SMEM ((2 * 24 * SC_WP + 8 * 4608) * 2)
__global__ void __launch_bounds__(256, 1) k_scan(const float* __restrict__ br) {
    extern __shared__ __nv_bfloat16 ssm[];
    __nv_bfloat16* Whi = ssm;
    __nv_bfloat16* Wlo = Whi + 24 * SC_WP;
    __nv_bfloat16* AB = Wlo + 24 * SC_WP;
    const int tid = threadIdx.x, wid = tid >> 5, lane = tid & 31;
    const int bid = blockIdx.x, u0 = bid * 8;

    for (int i = tid; i < 24 * 128; i += 256) {
        int n = i >> 7, j = (i & 127) * 8;
        *(uint4*)(Whi + n * SC_WP + j) = *(const uint4*)(g_rkhi + ((size_t)(bid * 24 + n)) * HH + j);
        *(uint4*)(Wlo + n * SC_WP + j) = *(const uint4*)(g_rklo + ((size_t)(bid * 24 + n)) * HH + j);
    }
    for (int i = tid; i < 128; i += 256) {
        uint4 z = {0, 0, 0, 0};
        *(uint4*)(g_hshi + (size_t)bid * HH + i * 8) = z;
        *(uint4*)(g_hslo + (size_t)bid * HH + i * 8) = z;
    }
    const int cc = 2 * (lane & 3);
    const float bz0 = br[u0 + cc], bz1 = br[u0 + cc + 1];
    const float brr0 = br[HH + u0 + cc], brr1 = br[HH + u0 + cc + 1];
    const float bh0 = br[2 * HH + u0 + cc], bh1 = br[2 * HH + u0 + cc + 1];
    float hp[4] = {0.f, 0.f, 0.f, 0.f};
    const int r1 = wid * 16 + (lane >> 2);
    const int b15 = lane & 15, bh8 = lane >> 4;
    const int b7 = lane & 7, bq = (lane >> 3) & 1;
    const int srow = lane >> 1, spart = (lane & 1) * 32;
    __nv_bfloat16* AW = AB + wid * 4608;
    const uint32_t aAddrBase = smem_u32(AW + (lane & 15) * AW_P + (lane >> 4) * 8);
    grid_barrier(SC_NB);

    for (int t = 0; t < TT; t++) {
        const float* xb = g_xg + (size_t)t * BB * 3072;
        float2 xz1 = *(const float2*)(xb + (size_t)r1 * 3072 + u0 + cc);
        float2 xr1 = *(const float2*)(xb + (size_t)r1 * 3072 + HH + u0 + cc);
        float2 xh1 = *(const float2*)(xb + (size_t)r1 * 3072 + 2 * HH + u0 + cc);
        float2 xz2 = *(const float2*)(xb + (size_t)(r1 + 8) * 3072 + u0 + cc);
        float2 xr2 = *(const float2*)(xb + (size_t)(r1 + 8) * 3072 + HH + u0 + cc);
        float2 xh2 = *(const float2*)(xb + (size_t)(r1 + 8) * 3072 + 2 * HH + u0 + cc);

        const __nv_bfloat16* Hhi = g_hshi + (size_t)t * BB * HH +
                                   (size_t)(wid * 16 + srow) * HH + spart;
        const __nv_bfloat16* Hlo = g_hslo + (size_t)t * BB * HH +
                                   (size_t)(wid * 16 + srow) * HH + spart;
        float acc[3][4];
#pragma unroll
        for (int i = 0; i < 3; i++)
#pragma unroll
            for (int j = 0; j < 4; j++) acc[i][j] = 0.f;

        uint4 ph[4], pl[4];
#pragma unroll
        for (int j = 0; j < 4; j++) {
            ph[j] = *(const uint4*)(Hhi + j * 8);
            pl[j] = *(const uint4*)(Hlo + j * 8);
        }
        {
            __nv_bfloat16* d = AW + srow * AW_P + spart;
#pragma unroll
            for (int j = 0; j < 4; j++) {
                *(uint4*)(d + j * 8) = ph[j];
                *(uint4*)(d + 1152 + j * 8) = pl[j];
            }
        }
        __syncwarp();

        for (int c = 0; c < 16; c++) {
            if (c < 15) {
#pragma unroll
                for (int j = 0; j < 4; j++) {
                    ph[j] = *(const uint4*)(Hhi + (c + 1) * 64 + j * 8);
                    pl[j] = *(const uint4*)(Hlo + (c + 1) * 64 + j * 8);
                }
            }
            const uint32_t aHi = aAddrBase + (uint32_t)((c & 1) * 2304 * 2);
            const uint32_t aLo = aHi + 1152 * 2;
#pragma unroll
            for (int kk = 0; kk < 4; kk++) {
                uint32_t ah[4], al[4];
                ldsm4(ah, aHi + kk * 32);
                ldsm4(al, aLo + kk * 32);
                const int kcol = c * 64 + kk * 16;
                uint32_t wh[4], wl[4], w2h[2], w2l[2];
                ldsm4(wh, smem_u32(Whi + b15 * SC_WP + kcol + bh8 * 8));
                ldsm4(wl, smem_u32(Wlo + b15 * SC_WP + kcol + bh8 * 8));
                ldsm2(w2h, smem_u32(Whi + (16 + b7) * SC_WP + kcol + bq * 8));
                ldsm2(w2l, smem_u32(Wlo + (16 + b7) * SC_WP + kcol + bq * 8));
                mma16816(acc[0], ah, wh[0], wh[2]);
                mma16816(acc[0], ah, wl[0], wl[2]);
                mma16816(acc[0], al, wh[0], wh[2]);
                mma16816(acc[1], ah, wh[1], wh[3]);
                mma16816(acc[1], ah, wl[1], wl[3]);
                mma16816(acc[1], al, wh[1], wh[3]);
                mma16816(acc[2], ah, w2h[0], w2h[1]);
                mma16816(acc[2], ah, w2l[0], w2l[1]);
                mma16816(acc[2], al, w2h[0], w2h[1]);
            }
            if (c < 15) {
                __nv_bfloat16* d = AW + ((c + 1) & 1) * 2304 + srow * AW_P + spart;
#pragma unroll
                for (int j = 0; j < 4; j++) {
                    *(uint4*)(d + j * 8) = ph[j];
                    *(uint4*)(d + 1152 + j * 8) = pl[j];
                }
            }
            __syncwarp();
        }
        {
            float z, r, hh;
            z = sigm(xz1.x + acc[0][0] + bz0);
            r = sigm(xr1.x + acc[1][0] + brr0);
            hh = tanhf(xh1.x + r * (acc[2][0] + bh0));
            hp[0] = z * hp[0] + (1.f - z) * hh;
            z = sigm(xz1.y + acc[0][1] + bz1);
            r = sigm(xr1.y + acc[1][1] + brr1);
            hh = tanhf(xh1.y + r * (acc[2][1] + bh1));
            hp[1] = z * hp[1] + (1.f - z) * hh;
            z = sigm(xz2.x + acc[0][2] + bz0);
            r = sigm(xr2.x + acc[1][2] + brr0);
            hh = tanhf(xh2.x + r * (acc[2][2] + bh0));
            hp[2] = z * hp[2] + (1.f - z) * hh;
            z = sigm(xz2.y + acc[0][3] + bz1);
            r = sigm(xr2.y + acc[1][3] + brr1);
            hh = tanhf(xh2.y + r * (acc[2][3] + bh1));
            hp[3] = z * hp[3] + (1.f - z) * hh;

            __nv_bfloat16 h0, l0, h1, l1;
            bsplit(hp[0], h0, l0); bsplit(hp[1], h1, l1);
            size_t o1 = ((size_t)(t + 1) * BB + r1) * HH + u0 + cc;
            *(__nv_bfloat162*)(g_hshi + o1) = __nv_bfloat162(h0, h1);
            *(__nv_bfloat162*)(g_hslo + o1) = __nv_bfloat162(l0, l1);
            bsplit(hp[2], h0, l0); bsplit(hp[3], h1, l1);
            size_t o2 = ((size_t)(t + 1) * BB + r1 + 8) * HH + u0 + cc;
            *(__nv_bfloat162*)(g_hshi + o2) = __nv_bfloat162(h0, h1);
            *(__nv_bfloat162*)(g_hslo + o2) = __nv_bfloat162(l0, l1);
        }
        __threadfence();
        grid_barrier(SC_NB);
    }
}

// =====================================================================
// k_mlp: d = relu(hs @ w1 + b1). grid (2 n-halves, 128 t), 256 thr, occ 2
// =====================================================================
#define MP 72
#define MLP_SMEM ((128 * MP + 64 * MP) * 2 * 2)
__global__ void __launch_bounds__(256, 2) k_mlp(const float* __restrict__ b1) {
    extern __shared__ __nv_bfloat16 msm[];
    __nv_bfloat16* Ahi = msm;
    __nv_bfloat16* Alo = Ahi + 128 * MP;
    __nv_bfloat16* Bhi = Alo + 128 * MP;
    __nv_bfloat16* Blo = Bhi + 64 * MP;
    __shared__ float sb[64];
    const int tid = threadIdx.x, wid = tid >> 5, lane = tid & 31;
    const int t = blockIdx.y, n0 = blockIdx.x * 64;
    if (tid < 64) sb[tid] = b1[n0 + tid];
    float acc[8][4];
#pragma unroll
    for (int i = 0; i < 8; i++)
#pragma unroll
        for (int j = 0; j < 4; j++) acc[i][j] = 0.f;
    const int arow = wid * 16 + (lane & 15), ahalf = lane >> 4;
    const int br15 = lane & 15, bh8 = lane >> 4;
    const int ar = tid >> 1, ap = (tid & 1) * 32;
    const int brr = tid >> 2, bp = (tid & 3) * 16;

    for (int kc = 0; kc < 16; kc++) {
        if (kc) __syncthreads();
        {
            const __nv_bfloat16* sh = g_hshi + ((size_t)(t + 1) * BB + ar) * HH + kc * 64 + ap;
            const __nv_bfloat16* sl = g_hslo + ((size_t)(t + 1) * BB + ar) * HH + kc * 64 + ap;
            *(uint4*)(Ahi + ar * MP + ap) = *(const uint4*)(sh);
            *(uint4*)(Ahi + ar * MP + ap + 8) = *(const uint4*)(sh + 8);
            *(uint4*)(Ahi + ar * MP + ap + 16) = *(const uint4*)(sh + 16);
            *(uint4*)(Ahi + ar * MP + ap + 24) = *(const uint4*)(sh + 24);
            *(uint4*)(Alo + ar * MP + ap) = *(const uint4*)(sl);
            *(uint4*)(Alo + ar * MP + ap + 8) = *(const uint4*)(sl + 8);
            *(uint4*)(Alo + ar * MP + ap + 16) = *(const uint4*)(sl + 16);
            *(uint4*)(Alo + ar * MP + ap + 24) = *(const uint4*)(sl + 24);
            const __nv_bfloat16* wh = g_w1hi + (size_t)(n0 + brr) * HH + kc * 64 + bp;
            const __nv_bfloat16* wl = g_w1lo + (size_t)(n0 + brr) * HH + kc * 64 + bp;
            *(uint4*)(Bhi + brr * MP + bp) = *(const uint4*)(wh);
            *(uint4*)(Bhi + brr * MP + bp + 8) = *(const uint4*)(wh + 8);
            *(uint4*)(Blo + brr * MP + bp) = *(const uint4*)(wl);
            *(uint4*)(Blo + brr * MP + bp + 8) = *(const uint4*)(wl + 8);
        }
        __syncthreads();
#pragma unroll
        for (int kk = 0; kk < 4; kk++) {
            uint32_t ah[4], al[4];
            ldsm4(ah, smem_u32(Ahi + arow * MP + ahalf * 8 + kk * 16));
            ldsm4(al, smem_u32(Alo + arow * MP + ahalf * 8 + kk * 16));
#pragma unroll
            for (int p = 0; p < 4; p++) {
                uint32_t bh[4], bl[4];
                ldsm4(bh, smem_u32(Bhi + (p * 16 + br15) * MP + kk * 16 + bh8 * 8));
                ldsm4(bl, smem_u32(Blo + (p * 16 + br15) * MP + kk * 16 + bh8 * 8));
                mma16816(acc[2 * p], ah, bh[0], bh[2]);
                mma16816(acc[2 * p], ah, bl[0], bl[2]);
                mma16816(acc[2 * p], al, bh[0], bh[2]);
                mma16816(acc[2 * p + 1], ah, bh[1], bh[3]);
                mma16816(acc[2 * p + 1], ah, bl[1], bl[3]);
                mma16816(acc[2 * p + 1], al, bh[1], bh[3]);
            }
        }
    }
    const int rr = wid * 16 + (lane >> 2), cc = 2 * (lane & 3);
    const int m1 = t * BB + rr, m2 = m1 + 8;
#pragma unroll
    for (int p = 0; p < 8; p++) {
        int col = p * 8 + cc;
        float d0 = fmaxf(acc[p][0] + sb[col], 0.f);
        float d1 = fmaxf(acc[p][1] + sb[col + 1], 0.f);
        float d2 = fmaxf(acc[p][2] + sb[col], 0.f);
        float d3 = fmaxf(acc[p][3] + sb[col + 1], 0.f);
        __nv_bfloat16 h0, l0, h1, l1;
        bsplit(d0, h0, l0); bsplit(d1, h1, l1);
        *(__nv_bfloat162*)(g_dhi + (size_t)m1 * DD + n0 + col) = __nv_bfloat162(h0, h1);
        *(__nv_bfloat162*)(g_dlo + (size_t)m1 * DD + n0 + col) = __nv_bfloat162(l0, l1);
        bsplit(d2, h0, l0); bsplit(d3, h1, l1);
        *(__nv_bfloat162*)(g_dhi + (size_t)m2 * DD + n0 + col) = __nv_bfloat162(h0, h1);
        *(__nv_bfloat162*)(g_dlo + (size_t)m2 * DD + n0 + col) = __nv_bfloat162(l0, l1);
    }
}

// =====================================================================
// k_logits v2: logits = d @ w2 + b2. grid (158 n-tiles of 64, 128 m).
// A fragments preloaded into registers (no loads in MMA loop), occ 2.
// =====================================================================
#define LBP 136
#define LG_SMEM (2 * 64 * LBP * 2)
__global__ void __launch_bounds__(256, 2) k_logits(const float* __restrict__ b2) {
    extern __shared__ __nv_bfloat16 lsm[];
    __nv_bfloat16* Bhi = lsm;
    __nv_bfloat16* Blo = Bhi + 64 * LBP;
    __shared__ float sb[64];
    const int tid = threadIdx.x, wid = tid >> 5, lane = tid & 31;
    const int m0 = blockIdx.y * 128, n0 = blockIdx.x * 64;
    if (tid < 64) sb[tid] = (n0 + tid < VV) ? b2[n0 + tid] : 0.f;
    {   // B: 64 rows x 128 k, each thread one quarter-row
        const int row = tid >> 2, part = (tid & 3) * 32;
        const __nv_bfloat16* wh = g_w2hi + (size_t)(n0 + row) * DD + part;
        const __nv_bfloat16* wl = g_w2lo + (size_t)(n0 + row) * DD + part;
#pragma unroll
        for (int j = 0; j < 32; j += 8) {
            *(uint4*)(Bhi + row * LBP + part + j) = *(const uint4*)(wh + j);
            *(uint4*)(Blo + row * LBP + part + j) = *(const uint4*)(wl + j);
        }
    }
    // A fragments preloaded to registers (K=128 -> 8 kt)
    const int r0 = wid * 16 + (lane >> 2);
    const int kq = (lane & 3) * 2;
    const __nv_bfloat16* dh0 = g_dhi + (size_t)(m0 + r0) * DD;
    const __nv_bfloat16* dh1 = g_dhi + (size_t)(m0 + r0 + 8) * DD;
    const __nv_bfloat16* dl0 = g_dlo + (size_t)(m0 + r0) * DD;
    const __nv_bfloat16* dl1 = g_dlo + (size_t)(m0 + r0 + 8) * DD;
    uint32_t Ah[8][4], Al[8][4];
#pragma unroll
    for (int kt = 0; kt < 8; kt++) {
        const int k0 = kt * 16 + kq;
        Ah[kt][0] = *(const uint32_t*)(dh0 + k0);
        Ah[kt][1] = *(const uint32_t*)(dh1 + k0);
        Ah[kt][2] = *(const uint32_t*)(dh0 + k0 + 8);
        Ah[kt][3] = *(const uint32_t*)(dh1 + k0 + 8);
        Al[kt][0] = *(const uint32_t*)(dl0 + k0);
        Al[kt][1] = *(const uint32_t*)(dl1 + k0);
        Al[kt][2] = *(const uint32_t*)(dl0 + k0 + 8);
        Al[kt][3] = *(const uint32_t*)(dl1 + k0 + 8);
    }
    __syncthreads();
    float acc[8][4];
#pragma unroll
    for (int i = 0; i < 8; i++)
#pragma unroll
        for (int j = 0; j < 4; j++) acc[i][j] = 0.f;
    const int br15 = lane & 15, bh8 = lane >> 4;
#pragma unroll
    for (int kt = 0; kt < 8; kt++) {
#pragma unroll
        for (int p = 0; p < 4; p++) {
            uint32_t bh[4], bl[4];
            ldsm4(bh, smem_u32(Bhi + (p * 16 + br15) * LBP + kt * 16 + bh8 * 8));
            ldsm4(bl, smem_u32(Blo + (p * 16 + br15) * LBP + kt * 16 + bh8 * 8));
            mma16816(acc[2 * p], Ah[kt], bh[0], bh[2]);
            mma16816(acc[2 * p], Ah[kt], bl[0], bl[2]);
            mma16816(acc[2 * p], Al[kt], bh[0], bh[2]);
            mma16816(acc[2 * p + 1], Ah[kt], bh[1], bh[3]);
            mma16816(acc[2 * p + 1], Ah[kt], bl[1], bl[3]);
            mma16816(acc[2 * p + 1], Al[kt], bh[1], bh[3]);
        }
    }
    const int rr = wid * 16 + (lane >> 2), cc = 2 * (lane & 3);
    float* o1 = g_logits + (size_t)(m0 + rr) * VV;
    float* o2 = g_logits + (size_t)(m0 + rr + 8) * VV;
#pragma unroll
    for (int p = 0; p < 8; p++) {
        int col = n0 + p * 8 + cc;
        if (col < VV) {
            float2 v0 = {acc[p][0] + sb[p * 8 + cc], acc[p][1] + sb[p * 8 + cc + 1]};
            float2 v1 = {acc[p][2] + sb[p * 8 + cc], acc[p][3] + sb[p * 8 + cc + 1]};
            *(float2*)(o1 + col) = v0;
            *(float2*)(o2 + col) = v1;
        }
    }
}

// =====================================================================
// k_softmax: 512 threads, online max+sum pass, then normalize-write.
// =====================================================================
__global__ __launch_bounds__(512) void k_softmax(float* __restrict__ out) {
    const int m = blockIdx.x;
    const int b = m & 127, t = m >> 7;
    const float* lr = g_logits + (size_t)m * VV;
    float* orow = out + ((size_t)b * TT + t) * VV;
    __shared__ float rm[16], rs[16];
    const int tid = threadIdx.x, lane = tid & 31, wid = tid >> 5;
    float mx = -1e30f, s = 0.f;
    for (int v = tid; v < VV; v += 512) {
        float x = lr[v] * 50.f;
        float nm = fmaxf(mx, x);
        s = s * __expf(mx - nm) + __expf(x - nm);
        mx = nm;
    }
#pragma unroll
    for (int o = 16; o; o >>= 1) {
        float om = __shfl_xor_sync(~0u, mx, o);
        float os = __shfl_xor_sync(~0u, s, o);
        float nm = fmaxf(mx, om);
        s = s * __expf(mx - nm) + os * __expf(om - nm);
        mx = nm;
    }
    if (lane == 0) { rm[wid] = mx; rs[wid] = s; }
    __syncthreads();
    if (tid == 0) {
        float M = rm[0], S = rs[0];
#pragma unroll
        for (int i = 1; i < 16; i++) {
            float nm = fmaxf(M, rm[i]);
            S = S * __expf(M - nm) + rs[i] * __expf(rm[i] - nm);
            M = nm;
        }
        rm[0] = M; rs[0] = 1.f / S;
    }
    __syncthreads();
    mx = rm[0];
    float inv = rs[0];
    for (int v = tid; v < VV; v += 512)
        orow[v] = __expf(lr[v] * 50.f - mx) * inv;
}

// =====================================================================
extern "C" void kernel_launch(void* const* d_in, const int* in_sizes, int n_in,
                              void* d_out, int out_size) {
    const int* tokens   = (const int*)d_in[0];
    const float* emb    = (const float*)d_in[1];
    const float* gru_k  = (const float*)d_in[2];
    const float* gru_rk = (const float*)d_in[3];
    const float* gru_bi = (const float*)d_in[4];
    const float* gru_br = (const float*)d_in[5];
    const float* w1     = (const float*)d_in[6];
    const float* b1     = (const float*)d_in[7];
    const float* w2     = (const float*)d_in[8];
    const float* b2     = (const float*)d_in[9];
    float* out = (float*)d_out;

    cudaFuncSetAttribute(k_xg, cudaFuncAttributeMaxDynamicSharedMemorySize, XG_SMEM);
    cudaFuncSetAttribute(k_scan, cudaFuncAttributeMaxDynamicSharedMemorySize, SCAN_SMEM);
    cudaFuncSetAttribute(k_mlp, cudaFuncAttributeMaxDynamicSharedMemorySize, MLP_SMEM);
    cudaFuncSetAttribute(k_logits, cudaFuncAttributeMaxDynamicSharedMemorySize, LG_SMEM);

    k_split<<<2048, 256>>>(emb, gru_k, gru_rk, w1, w2);
    k_xg<<<dim3(24, 128), 256, XG_SMEM>>>(tokens, gru_bi);
    k_scan<<<SC_NB, 256, SCAN_SMEM>>>(gru_br);
    k_mlp<<<dim3(2, 128), 256, MLP_SMEM>>>(b1);
    k_logits<<<dim3(158, 128), 256, LG_SMEM>>>(b2);
    k_softmax<<<TT * BB, 512>>>(out);
}

// round 12
// speedup vs baseline: 1.2250x; 1.0584x over previous
#include <cuda_runtime.h>
#include <cuda_bf16.h>
#include <cstdint>

#define BB 128
#define TT 128
#define VV 10000
#define VP 10112
#define EE 256
#define HH 1024
#define DD 128

// ------------------- device scratch (no allocs) -------------------
__device__ __nv_bfloat16 g_ehi[(size_t)VV * EE], g_elo[(size_t)VV * EE];      // [tok][k]
__device__ __nv_bfloat16 g_gkhi[(size_t)3 * HH * EE], g_gklo[(size_t)3 * HH * EE]; // [n][k]
__device__ __nv_bfloat16 g_rkhi[(size_t)3 * HH * HH], g_rklo[(size_t)3 * HH * HH]; // [row][k]
__device__ __nv_bfloat16 g_w1hi[(size_t)DD * HH], g_w1lo[(size_t)DD * HH];    // [n][k]
__device__ __nv_bfloat16 g_w2hi[(size_t)VP * DD], g_w2lo[(size_t)VP * DD];    // [n][k]
__device__ float g_xg[(size_t)TT * BB * 3 * HH];                              // [t][b][3072]
__device__ __nv_bfloat16 g_hshi[(size_t)(TT + 1) * BB * HH];
__device__ __nv_bfloat16 g_hslo[(size_t)(TT + 1) * BB * HH];
__device__ __nv_bfloat16 g_dhi[(size_t)TT * BB * DD], g_dlo[(size_t)TT * BB * DD];
__device__ float g_logits[(size_t)TT * BB * VV];
__device__ unsigned g_bar_cnt = 0, g_bar_phase = 0;

// ------------------- helpers -------------------
__device__ __forceinline__ uint32_t smem_u32(const void* p) {
    uint32_t a;
    asm("{ .reg .u64 t; cvta.to.shared.u64 t, %1; cvt.u32.u64 %0, t; }"
        : "=r"(a) : "l"(p));
    return a;
}
__device__ __forceinline__ void ldsm4(uint32_t* r, uint32_t a) {
    asm volatile("ldmatrix.sync.aligned.m8n8.x4.shared.b16 {%0,%1,%2,%3}, [%4];"
                 : "=r"(r[0]), "=r"(r[1]), "=r"(r[2]), "=r"(r[3]) : "r"(a));
}
__device__ __forceinline__ void ldsm2(uint32_t* r, uint32_t a) {
    asm volatile("ldmatrix.sync.aligned.m8n8.x2.shared.b16 {%0,%1}, [%2];"
                 : "=r"(r[0]), "=r"(r[1]) : "r"(a));
}
__device__ __forceinline__ void mma16816(float* c, const uint32_t* a,
                                         uint32_t b0, uint32_t b1) {
    asm volatile(
        "mma.sync.aligned.m16n8k16.row.col.f32.bf16.bf16.f32 "
        "{%0,%1,%2,%3}, {%4,%5,%6,%7}, {%8,%9}, {%0,%1,%2,%3};"
        : "+f"(c[0]), "+f"(c[1]), "+f"(c[2]), "+f"(c[3])
        : "r"(a[0]), "r"(a[1]), "r"(a[2]), "r"(a[3]), "r"(b0), "r"(b1));
}
__device__ __forceinline__ void bsplit(float v, __nv_bfloat16& h, __nv_bfloat16& l) {
    h = __float2bfloat16(v);
    l = __float2bfloat16(v - __bfloat162float(h));
}
__device__ __forceinline__ float sigm(float x) { return 1.f / (1.f + __expf(-x)); }

__device__ __forceinline__ void grid_barrier(int nblk) {
    __syncthreads();
    if (threadIdx.x == 0) {
        __threadfence();
        unsigned ph = *(volatile unsigned*)&g_bar_phase;
        unsigned old = atomicAdd(&g_bar_cnt, 1);
        if (old == (unsigned)(nblk - 1)) {
            g_bar_cnt = 0;
            __threadfence();
            atomicAdd(&g_bar_phase, 1);
        } else {
            while (*(volatile unsigned*)&g_bar_phase == ph) { __nanosleep(32); }
        }
        __threadfence();
    }
    __syncthreads();
}

// =====================================================================
// k_split: pre-split weights into bf16 hi/lo, B-layouts
// =====================================================================
__global__ __launch_bounds__(256) void k_split(const float* __restrict__ emb,
                                               const float* __restrict__ gk,
                                               const float* __restrict__ rk,
                                               const float* __restrict__ w1,
                                               const float* __restrict__ w2) {
    const size_t stride = (size_t)gridDim.x * blockDim.x;
    const size_t t0 = (size_t)blockIdx.x * blockDim.x + threadIdx.x;
    for (size_t i = t0; i < (size_t)VV * EE; i += stride)
        bsplit(emb[i], g_ehi[i], g_elo[i]);
    for (size_t i = t0; i < (size_t)3 * HH * EE; i += stride) {
        int n = (int)(i % (3 * HH)), k = (int)(i / (3 * HH));
        bsplit(gk[(size_t)k * 3 * HH + n], g_gkhi[(size_t)n * EE + k],
               g_gklo[(size_t)n * EE + k]);
    }
    for (size_t i = t0; i < (size_t)3 * HH * HH; i += stride) {
        int c = (int)(i % (3 * HH)), k = (int)(i / (3 * HH));
        int row = ((c & 1023) >> 3) * 24 + (c >> 10) * 8 + (c & 7);
        bsplit(rk[(size_t)k * 3 * HH + c], g_rkhi[(size_t)row * HH + k],
               g_rklo[(size_t)row * HH + k]);
    }
    for (size_t i = t0; i < (size_t)DD * HH; i += stride) {
        int n = (int)(i % DD), k = (int)(i / DD);
        bsplit(w1[(size_t)k * DD + n], g_w1hi[(size_t)n * HH + k],
               g_w1lo[(size_t)n * HH + k]);
    }
    for (size_t i = t0; i < (size_t)VP * DD; i += stride) {
        int n = (int)(i % VP), k = (int)(i / VP);
        float v = (n < VV) ? w2[(size_t)k * VV + n] : 0.f;
        bsplit(v, g_w2hi[(size_t)n * DD + k], g_w2lo[(size_t)n * DD + k]);
    }
}

// =====================================================================
// k_xg: xg = emb[tok] @ gru_k + bi.  grid (24 n-tiles, 128 t), 256 thr
// B staged in smem per 128-k chunk; A fragments direct LDG (occ 2).
// =====================================================================
#define BP 136
#define XG_SMEM (2 * 128 * BP * 2)
__global__ void __launch_bounds__(256, 2)
k_xg(const int* __restrict__ tokens, const float* __restrict__ bi) {
    extern __shared__ __nv_bfloat16 xsm[];
    __nv_bfloat16* Bhi = xsm;
    __nv_bfloat16* Blo = Bhi + 128 * BP;
    __shared__ float sb[128];
    __shared__ int toks[128];
    const int tid = threadIdx.x, wid = tid >> 5, lane = tid & 31;
    const int t = blockIdx.y, n0 = blockIdx.x * 128;
    if (tid < 128) {
        sb[tid] = bi[n0 + tid];
        toks[tid] = tokens[tid * TT + t];
    }
    __syncthreads();
    const int r0 = wid * 16 + (lane >> 2);
    const int kq = (lane & 3) * 2;
    const __nv_bfloat16* eh0 = g_ehi + (size_t)toks[r0] * EE;
    const __nv_bfloat16* eh1 = g_ehi + (size_t)toks[r0 + 8] * EE;
    const __nv_bfloat16* el0 = g_elo + (size_t)toks[r0] * EE;
    const __nv_bfloat16* el1 = g_elo + (size_t)toks[r0 + 8] * EE;

    float acc[16][4];
#pragma unroll
    for (int i = 0; i < 16; i++)
#pragma unroll
        for (int j = 0; j < 4; j++) acc[i][j] = 0.f;
    const int br15 = lane & 15, bh8 = lane >> 4;
    const int lr = tid >> 1, lp = tid & 1;

    for (int kc = 0; kc < 2; kc++) {
        if (kc) __syncthreads();
        {
            const __nv_bfloat16* sh = g_gkhi + (size_t)(n0 + lr) * EE + kc * 128 + lp * 64;
            const __nv_bfloat16* sl = g_gklo + (size_t)(n0 + lr) * EE + kc * 128 + lp * 64;
#pragma unroll
            for (int j = 0; j < 64; j += 8) {
                *(uint4*)(Bhi + lr * BP + lp * 64 + j) = *(const uint4*)(sh + j);
                *(uint4*)(Blo + lr * BP + lp * 64 + j) = *(const uint4*)(sl + j);
            }
        }
        __syncthreads();
#pragma unroll
        for (int kt = 0; kt < 8; kt++) {
            const int k0 = kc * 128 + kt * 16 + kq;
            uint32_t ah[4], al[4];
            ah[0] = *(const uint32_t*)(eh0 + k0);
            ah[1] = *(const uint32_t*)(eh1 + k0);
            ah[2] = *(const uint32_t*)(eh0 + k0 + 8);
            ah[3] = *(const uint32_t*)(eh1 + k0 + 8);
            al[0] = *(const uint32_t*)(el0 + k0);
            al[1] = *(const uint32_t*)(el1 + k0);
            al[2] = *(const uint32_t*)(el0 + k0 + 8);
            al[3] = *(const uint32_t*)(el1 + k0 + 8);
#pragma unroll
            for (int p = 0; p < 8; p++) {
                uint32_t bh[4], bl[4];
                ldsm4(bh, smem_u32(Bhi + (p * 16 + br15) * BP + kt * 16 + bh8 * 8));
                ldsm4(bl, smem_u32(Blo + (p * 16 + br15) * BP + kt * 16 + bh8 * 8));
                mma16816(acc[2 * p], ah, bh[0], bh[2]);
                mma16816(acc[2 * p], ah, bl[0], bl[2]);
                mma16816(acc[2 * p], al, bh[0], bh[2]);
                mma16816(acc[2 * p + 1], ah, bh[1], bh[3]);
                mma16816(acc[2 * p + 1], ah, bl[1], bl[3]);
                mma16816(acc[2 * p + 1], al, bh[1], bh[3]);
            }
        }
    }
    const int rr = wid * 16 + (lane >> 2), cc = 2 * (lane & 3);
    float* outb = g_xg + (size_t)t * BB * 3072 + n0;
#pragma unroll
    for (int p = 0; p < 16; p++) {
        int col = p * 8 + cc;
        float2 v0 = {acc[p][0] + sb[col], acc[p][1] + sb[col + 1]};
        float2 v1 = {acc[p][2] + sb[col], acc[p][3] + sb[col + 1]};
        *(float2*)(outb + (size_t)rr * 3072 + col) = v0;
        *(float2*)(outb + (size_t)(rr + 8) * 3072 + col) = v1;
    }
}

// =====================================================================
// k_scan: persistent GRU scan, warp-private A staging (no block syncs
// inside k-loop). 128 blocks x 256 thr; block owns 8 units (24 cols).
// (exact R5 version — best measured)
// =====================================================================
#define SC_NB 128
#define SC_WP 1032
#define AW_P 72
#define SCAN_SMEM ((2 * 24 * SC_WP + 8 * 4608) * 2)
__global__ void __launch_bounds__(256, 1) k_scan(const float* __restrict__ br) {
    extern __shared__ __nv_bfloat16 ssm[];
    __nv_bfloat16* Whi = ssm;
    __nv_bfloat16* Wlo = Whi + 24 * SC_WP;
    __nv_bfloat16* AB = Wlo + 24 * SC_WP;
    const int tid = threadIdx.x, wid = tid >> 5, lane = tid & 31;
    const int bid = blockIdx.x, u0 = bid * 8;

    for (int i = tid; i < 24 * 128; i += 256) {
        int n = i >> 7, j = (i & 127) * 8;
        *(uint4*)(Whi + n * SC_WP + j) = *(const uint4*)(g_rkhi + ((size_t)(bid * 24 + n)) * HH + j);
        *(uint4*)(Wlo + n * SC_WP + j) = *(const uint4*)(g_rklo + ((size_t)(bid * 24 + n)) * HH + j);
    }
    for (int i = tid; i < 128; i += 256) {
        uint4 z = {0, 0, 0, 0};
        *(uint4*)(g_hshi + (size_t)bid * HH + i * 8) = z;
        *(uint4*)(g_hslo + (size_t)bid * HH + i * 8) = z;
    }
    const int cc = 2 * (lane & 3);
    const float bz0 = br[u0 + cc], bz1 = br[u0 + cc + 1];
    const float brr0 = br[HH + u0 + cc], brr1 = br[HH + u0 + cc + 1];
    const float bh0 = br[2 * HH + u0 + cc], bh1 = br[2 * HH + u0 + cc + 1];
    float hp[4] = {0.f, 0.f, 0.f, 0.f};
    const int r1 = wid * 16 + (lane >> 2);
    const int b15 = lane & 15, bh8 = lane >> 4;
    const int b7 = lane & 7, bq = (lane >> 3) & 1;
    const int srow = lane >> 1, spart = (lane & 1) * 32;
    __nv_bfloat16* AW = AB + wid * 4608;
    const uint32_t aAddrBase = smem_u32(AW + (lane & 15) * AW_P + (lane >> 4) * 8);
    grid_barrier(SC_NB);

    for (int t = 0; t < TT; t++) {
        const float* xb = g_xg + (size_t)t * BB * 3072;
        float2 xz1 = *(const float2*)(xb + (size_t)r1 * 3072 + u0 + cc);
        float2 xr1 = *(const float2*)(xb + (size_t)r1 * 3072 + HH + u0 + cc);
        float2 xh1 = *(const float2*)(xb + (size_t)r1 * 3072 + 2 * HH + u0 + cc);
        float2 xz2 = *(const float2*)(xb + (size_t)(r1 + 8) * 3072 + u0 + cc);
        float2 xr2 = *(const float2*)(xb + (size_t)(r1 + 8) * 3072 + HH + u0 + cc);
        float2 xh2 = *(const float2*)(xb + (size_t)(r1 + 8) * 3072 + 2 * HH + u0 + cc);

        const __nv_bfloat16* Hhi = g_hshi + (size_t)t * BB * HH +
                                   (size_t)(wid * 16 + srow) * HH + spart;
        const __nv_bfloat16* Hlo = g_hslo + (size_t)t * BB * HH +
                                   (size_t)(wid * 16 + srow) * HH + spart;
        float acc[3][4];
#pragma unroll
        for (int i = 0; i < 3; i++)
#pragma unroll
            for (int j = 0; j < 4; j++) acc[i][j] = 0.f;

        uint4 ph[4], pl[4];
#pragma unroll
        for (int j = 0; j < 4; j++) {
            ph[j] = *(const uint4*)(Hhi + j * 8);
            pl[j] = *(const uint4*)(Hlo + j * 8);
        }
        {
            __nv_bfloat16* d = AW + srow * AW_P + spart;
#pragma unroll
            for (int j = 0; j < 4; j++) {
                *(uint4*)(d + j * 8) = ph[j];
                *(uint4*)(d + 1152 + j * 8) = pl[j];
            }
        }
        __syncwarp();

        for (int c = 0; c < 16; c++) {
            if (c < 15) {
#pragma unroll
                for (int j = 0; j < 4; j++) {
                    ph[j] = *(const uint4*)(Hhi + (c + 1) * 64 + j * 8);
                    pl[j] = *(const uint4*)(Hlo + (c + 1) * 64 + j * 8);
                }
            }
            const uint32_t aHi = aAddrBase + (uint32_t)((c & 1) * 2304 * 2);
            const uint32_t aLo = aHi + 1152 * 2;
#pragma unroll
            for (int kk = 0; kk < 4; kk++) {
                uint32_t ah[4], al[4];
                ldsm4(ah, aHi + kk * 32);
                ldsm4(al, aLo + kk * 32);
                const int kcol = c * 64 + kk * 16;
                uint32_t wh[4], wl[4], w2h[2], w2l[2];
                ldsm4(wh, smem_u32(Whi + b15 * SC_WP + kcol + bh8 * 8));
                ldsm4(wl, smem_u32(Wlo + b15 * SC_WP + kcol + bh8 * 8));
                ldsm2(w2h, smem_u32(Whi + (16 + b7) * SC_WP + kcol + bq * 8));
                ldsm2(w2l, smem_u32(Wlo + (16 + b7) * SC_WP + kcol + bq * 8));
                mma16816(acc[0], ah, wh[0], wh[2]);
                mma16816(acc[0], ah, wl[0], wl[2]);
                mma16816(acc[0], al, wh[0], wh[2]);
                mma16816(acc[1], ah, wh[1], wh[3]);
                mma16816(acc[1], ah, wl[1], wl[3]);
                mma16816(acc[1], al, wh[1], wh[3]);
                mma16816(acc[2], ah, w2h[0], w2h[1]);
                mma16816(acc[2], ah, w2l[0], w2l[1]);
                mma16816(acc[2], al, w2h[0], w2h[1]);
            }
            if (c < 15) {
                __nv_bfloat16* d = AW + ((c + 1) & 1) * 2304 + srow * AW_P + spart;
#pragma unroll
                for (int j = 0; j < 4; j++) {
                    *(uint4*)(d + j * 8) = ph[j];
                    *(uint4*)(d + 1152 + j * 8) = pl[j];
                }
            }
            __syncwarp();
        }
        {
            float z, r, hh;
            z = sigm(xz1.x + acc[0][0] + bz0);
            r = sigm(xr1.x + acc[1][0] + brr0);
            hh = tanhf(xh1.x + r * (acc[2][0] + bh0));
            hp[0] = z * hp[0] + (1.f - z) * hh;
            z = sigm(xz1.y + acc[0][1] + bz1);
            r = sigm(xr1.y + acc[1][1] + brr1);
            hh = tanhf(xh1.y + r * (acc[2][1] + bh1));
            hp[1] = z * hp[1] + (1.f - z) * hh;
            z = sigm(xz2.x + acc[0][2] + bz0);
            r = sigm(xr2.x + acc[1][2] + brr0);
            hh = tanhf(xh2.x + r * (acc[2][2] + bh0));
            hp[2] = z * hp[2] + (1.f - z) * hh;
            z = sigm(xz2.y + acc[0][3] + bz1);
            r = sigm(xr2.y + acc[1][3] + brr1);
            hh = tanhf(xh2.y + r * (acc[2][3] + bh1));
            hp[3] = z * hp[3] + (1.f - z) * hh;

            __nv_bfloat16 h0, l0, h1, l1;
            bsplit(hp[0], h0, l0); bsplit(hp[1], h1, l1);
            size_t o1 = ((size_t)(t + 1) * BB + r1) * HH + u0 + cc;
            *(__nv_bfloat162*)(g_hshi + o1) = __nv_bfloat162(h0, h1);
            *(__nv_bfloat162*)(g_hslo + o1) = __nv_bfloat162(l0, l1);
            bsplit(hp[2], h0, l0); bsplit(hp[3], h1, l1);
            size_t o2 = ((size_t)(t + 1) * BB + r1 + 8) * HH + u0 + cc;
            *(__nv_bfloat162*)(g_hshi + o2) = __nv_bfloat162(h0, h1);
            *(__nv_bfloat162*)(g_hslo + o2) = __nv_bfloat162(l0, l1);
        }
        __threadfence();
        grid_barrier(SC_NB);
    }
}

// =====================================================================
// k_mlp: d = relu(hs @ w1 + b1). grid (2 n-halves, 128 t), 256 thr, occ 2
// (R7 version — ncu-verified 96->75us)
// =====================================================================
#define MP 72
#define MLP_SMEM ((128 * MP + 64 * MP) * 2 * 2)
__global__ void __launch_bounds__(256, 2) k_mlp(const float* __restrict__ b1) {
    extern __shared__ __nv_bfloat16 msm[];
    __nv_bfloat16* Ahi = msm;
    __nv_bfloat16* Alo = Ahi + 128 * MP;
    __nv_bfloat16* Bhi = Alo + 128 * MP;
    __nv_bfloat16* Blo = Bhi + 64 * MP;
    __shared__ float sb[64];
    const int tid = threadIdx.x, wid = tid >> 5, lane = tid & 31;
    const int t = blockIdx.y, n0 = blockIdx.x * 64;
    if (tid < 64) sb[tid] = b1[n0 + tid];
    float acc[8][4];
#pragma unroll
    for (int i = 0; i < 8; i++)
#pragma unroll
        for (int j = 0; j < 4; j++) acc[i][j] = 0.f;
    const int arow = wid * 16 + (lane & 15), ahalf = lane >> 4;
    const int br15 = lane & 15, bh8 = lane >> 4;
    const int ar = tid >> 1, ap = (tid & 1) * 32;
    const int brr = tid >> 2, bp = (tid & 3) * 16;

    for (int kc = 0; kc < 16; kc++) {
        if (kc) __syncthreads();
        {
            const __nv_bfloat16* sh = g_hshi + ((size_t)(t + 1) * BB + ar) * HH + kc * 64 + ap;
            const __nv_bfloat16* sl = g_hslo + ((size_t)(t + 1) * BB + ar) * HH + kc * 64 + ap;
            *(uint4*)(Ahi + ar * MP + ap) = *(const uint4*)(sh);
            *(uint4*)(Ahi + ar * MP + ap + 8) = *(const uint4*)(sh + 8);
            *(uint4*)(Ahi + ar * MP + ap + 16) = *(const uint4*)(sh + 16);
            *(uint4*)(Ahi + ar * MP + ap + 24) = *(const uint4*)(sh + 24);
            *(uint4*)(Alo + ar * MP + ap) = *(const uint4*)(sl);
            *(uint4*)(Alo + ar * MP + ap + 8) = *(const uint4*)(sl + 8);
            *(uint4*)(Alo + ar * MP + ap + 16) = *(const uint4*)(sl + 16);
            *(uint4*)(Alo + ar * MP + ap + 24) = *(const uint4*)(sl + 24);
            const __nv_bfloat16* wh = g_w1hi + (size_t)(n0 + brr) * HH + kc * 64 + bp;
            const __nv_bfloat16* wl = g_w1lo + (size_t)(n0 + brr) * HH + kc * 64 + bp;
            *(uint4*)(Bhi + brr * MP + bp) = *(const uint4*)(wh);
            *(uint4*)(Bhi + brr * MP + bp + 8) = *(const uint4*)(wh + 8);
            *(uint4*)(Blo + brr * MP + bp) = *(const uint4*)(wl);
            *(uint4*)(Blo + brr * MP + bp + 8) = *(const uint4*)(wl + 8);
        }
        __syncthreads();
#pragma unroll
        for (int kk = 0; kk < 4; kk++) {
            uint32_t ah[4], al[4];
            ldsm4(ah, smem_u32(Ahi + arow * MP + ahalf * 8 + kk * 16));
            ldsm4(al, smem_u32(Alo + arow * MP + ahalf * 8 + kk * 16));
#pragma unroll
            for (int p = 0; p < 4; p++) {
                uint32_t bh[4], bl[4];
                ldsm4(bh, smem_u32(Bhi + (p * 16 + br15) * MP + kk * 16 + bh8 * 8));
                ldsm4(bl, smem_u32(Blo + (p * 16 + br15) * MP + kk * 16 + bh8 * 8));
                mma16816(acc[2 * p], ah, bh[0], bh[2]);
                mma16816(acc[2 * p], ah, bl[0], bl[2]);
                mma16816(acc[2 * p], al, bh[0], bh[2]);
                mma16816(acc[2 * p + 1], ah, bh[1], bh[3]);
                mma16816(acc[2 * p + 1], ah, bl[1], bl[3]);
                mma16816(acc[2 * p + 1], al, bh[1], bh[3]);
            }
        }
    }
    const int rr = wid * 16 + (lane >> 2), cc = 2 * (lane & 3);
    const int m1 = t * BB + rr, m2 = m1 + 8;
#pragma unroll
    for (int p = 0; p < 8; p++) {
        int col = p * 8 + cc;
        float d0 = fmaxf(acc[p][0] + sb[col], 0.f);
        float d1 = fmaxf(acc[p][1] + sb[col + 1], 0.f);
        float d2 = fmaxf(acc[p][2] + sb[col], 0.f);
        float d3 = fmaxf(acc[p][3] + sb[col + 1], 0.f);
        __nv_bfloat16 h0, l0, h1, l1;
        bsplit(d0, h0, l0); bsplit(d1, h1, l1);
        *(__nv_bfloat162*)(g_dhi + (size_t)m1 * DD + n0 + col) = __nv_bfloat162(h0, h1);
        *(__nv_bfloat162*)(g_dlo + (size_t)m1 * DD + n0 + col) = __nv_bfloat162(l0, l1);
        bsplit(d2, h0, l0); bsplit(d3, h1, l1);
        *(__nv_bfloat162*)(g_dhi + (size_t)m2 * DD + n0 + col) = __nv_bfloat162(h0, h1);
        *(__nv_bfloat162*)(g_dlo + (size_t)m2 * DD + n0 + col) = __nv_bfloat162(l0, l1);
    }
}

// =====================================================================
// k_logits: logits = d @ w2 + b2. grid (79 n, 128 m), 256 thr, occ 2
// (exact R5 version)
// =====================================================================
#define LG_SMEM (2 * 128 * BP * 2)
__global__ void __launch_bounds__(256, 2) k_logits(const float* __restrict__ b2) {
    extern __shared__ __nv_bfloat16 lsm[];
    __nv_bfloat16* Bhi = lsm;
    __nv_bfloat16* Blo = Bhi + 128 * BP;
    __shared__ float sb[128];
    const int tid = threadIdx.x, wid = tid >> 5, lane = tid & 31;
    const int m0 = blockIdx.y * 128, n0 = blockIdx.x * 128;
    if (tid < 128) sb[tid] = (n0 + tid < VV) ? b2[n0 + tid] : 0.f;
    {
        const int lr = tid >> 1, lp = tid & 1;
        const __nv_bfloat16* wh = g_w2hi + (size_t)(n0 + lr) * DD + lp * 64;
        const __nv_bfloat16* wl = g_w2lo + (size_t)(n0 + lr) * DD + lp * 64;
#pragma unroll
        for (int j = 0; j < 64; j += 8) {
            *(uint4*)(Bhi + lr * BP + lp * 64 + j) = *(const uint4*)(wh + j);
            *(uint4*)(Blo + lr * BP + lp * 64 + j) = *(const uint4*)(wl + j);
        }
    }
    __syncthreads();
    float acc[16][4];
#pragma unroll
    for (int i = 0; i < 16; i++)
#pragma unroll
        for (int j = 0; j < 4; j++) acc[i][j] = 0.f;
    const int r0 = wid * 16 + (lane >> 2);
    const int kq = (lane & 3) * 2;
    const __nv_bfloat16* dh0 = g_dhi + (size_t)(m0 + r0) * DD;
    const __nv_bfloat16* dh1 = g_dhi + (size_t)(m0 + r0 + 8) * DD;
    const __nv_bfloat16* dl0 = g_dlo + (size_t)(m0 + r0) * DD;
    const __nv_bfloat16* dl1 = g_dlo + (size_t)(m0 + r0 + 8) * DD;
    const int br15 = lane & 15, bh8 = lane >> 4;
#pragma unroll
    for (int kt = 0; kt < 8; kt++) {
        const int k0 = kt * 16 + kq;
        uint32_t ah[4], al[4];
        ah[0] = *(const uint32_t*)(dh0 + k0);
        ah[1] = *(const uint32_t*)(dh1 + k0);
        ah[2] = *(const uint32_t*)(dh0 + k0 + 8);
        ah[3] = *(const uint32_t*)(dh1 + k0 + 8);
        al[0] = *(const uint32_t*)(dl0 + k0);
        al[1] = *(const uint32_t*)(dl1 + k0);
        al[2] = *(const uint32_t*)(dl0 + k0 + 8);
        al[3] = *(const uint32_t*)(dl1 + k0 + 8);
#pragma unroll
        for (int p = 0; p < 8; p++) {
            uint32_t bh[4], bl[4];
            ldsm4(bh, smem_u32(Bhi + (p * 16 + br15) * BP + kt * 16 + bh8 * 8));
            ldsm4(bl, smem_u32(Blo + (p * 16 + br15) * BP + kt * 16 + bh8 * 8));
            mma16816(acc[2 * p], ah, bh[0], bh[2]);
            mma16816(acc[2 * p], ah, bl[0], bl[2]);
            mma16816(acc[2 * p], al, bh[0], bh[2]);
            mma16816(acc[2 * p + 1], ah, bh[1], bh[3]);
            mma16816(acc[2 * p + 1], ah, bl[1], bl[3]);
            mma16816(acc[2 * p + 1], al, bh[1], bh[3]);
        }
    }
    const int rr = wid * 16 + (lane >> 2), cc = 2 * (lane & 3);
    float* o1 = g_logits + (size_t)(m0 + rr) * VV;
    float* o2 = g_logits + (size_t)(m0 + rr + 8) * VV;
#pragma unroll
    for (int p = 0; p < 16; p++) {
        int col = n0 + p * 8 + cc;
        if (col < VV) {
            float2 v0 = {acc[p][0] + sb[p * 8 + cc], acc[p][1] + sb[p * 8 + cc + 1]};
            float2 v1 = {acc[p][2] + sb[p * 8 + cc], acc[p][3] + sb[p * 8 + cc + 1]};
            *(float2*)(o1 + col) = v0;
            *(float2*)(o2 + col) = v1;
        }
    }
}

// =====================================================================
// k_softmax: online max+sum pass, then normalize-write. TEMP=0.02
// (exact R5 version, 256 threads)
// =====================================================================
__global__ __launch_bounds__(256) void k_softmax(float* __restrict__ out) {
    const int m = blockIdx.x;
    const int b = m & 127, t = m >> 7;
    const float* lr = g_logits + (size_t)m * VV;
    float* orow = out + ((size_t)b * TT + t) * VV;
    __shared__ float rm[8], rs[8];
    const int tid = threadIdx.x, lane = tid & 31, wid = tid >> 5;
    float mx = -1e30f, s = 0.f;
    for (int v = tid; v < VV; v += 256) {
        float x = lr[v] * 50.f;
        float nm = fmaxf(mx, x);
        s = s * __expf(mx - nm) + __expf(x - nm);
        mx = nm;
    }
#pragma unroll
    for (int o = 16; o; o >>= 1) {
        float om = __shfl_xor_sync(~0u, mx, o);
        float os = __shfl_xor_sync(~0u, s, o);
        float nm = fmaxf(mx, om);
        s = s * __expf(mx - nm) + os * __expf(om - nm);
        mx = nm;
    }
    if (lane == 0) { rm[wid] = mx; rs[wid] = s; }
    __syncthreads();
    if (tid == 0) {
        float M = rm[0], S = rs[0];
#pragma unroll
        for (int i = 1; i < 8; i++) {
            float nm = fmaxf(M, rm[i]);
            S = S * __expf(M - nm) + rs[i] * __expf(rm[i] - nm);
            M = nm;
        }
        rm[0] = M; rs[0] = 1.f / S;
    }
    __syncthreads();
    mx = rm[0];
    float inv = rs[0];
    for (int v = tid; v < VV; v += 256)
        orow[v] = __expf(lr[v] * 50.f - mx) * inv;
}

// =====================================================================
extern "C" void kernel_launch(void* const* d_in, const int* in_sizes, int n_in,
                              void* d_out, int out_size) {
    const int* tokens   = (const int*)d_in[0];
    const float* emb    = (const float*)d_in[1];
    const float* gru_k  = (const float*)d_in[2];
    const float* gru_rk = (const float*)d_in[3];
    const float* gru_bi = (const float*)d_in[4];
    const float* gru_br = (const float*)d_in[5];
    const float* w1     = (const float*)d_in[6];
    const float* b1     = (const float*)d_in[7];
    const float* w2     = (const float*)d_in[8];
    const float* b2     = (const float*)d_in[9];
    float* out = (float*)d_out;

    cudaFuncSetAttribute(k_xg, cudaFuncAttributeMaxDynamicSharedMemorySize, XG_SMEM);
    cudaFuncSetAttribute(k_scan, cudaFuncAttributeMaxDynamicSharedMemorySize, SCAN_SMEM);
    cudaFuncSetAttribute(k_mlp, cudaFuncAttributeMaxDynamicSharedMemorySize, MLP_SMEM);
    cudaFuncSetAttribute(k_logits, cudaFuncAttributeMaxDynamicSharedMemorySize, LG_SMEM);

    k_split<<<2048, 256>>>(emb, gru_k, gru_rk, w1, w2);
    k_xg<<<dim3(24, 128), 256, XG_SMEM>>>(tokens, gru_bi);
    k_scan<<<SC_NB, 256, SCAN_SMEM>>>(gru_br);
    k_mlp<<<dim3(2, 128), 256, MLP_SMEM>>>(b1);
    k_logits<<<dim3(79, 128), 256, LG_SMEM>>>(b2);
    k_softmax<<<TT * BB, 256>>>(out);
}